// round 8
// baseline (speedup 1.0000x reference)
#include <cuda_runtime.h>

#define BATCH   64
#define NPTS    4096
#define NFRAMES 100
#define CHUNKS  4
#define FSPLIT  2
#define FPER    (NFRAMES / FSPLIT)   // 50 frames per CTA
#define TPB     256
#define KPT     4   // NPTS / (CHUNKS*TPB)
#define GRID    (BATCH * CHUNKS * FSPLIT)

__device__ double g_sum;
__device__ double g_msum;
__device__ unsigned int g_count;

typedef unsigned long long u64;

// ---- f32x2 packed helpers (Blackwell sm_100+); packed pair carried as u64 ----
__device__ __forceinline__ u64 pack2(float lo, float hi) {
    u64 d;
    asm("mov.b64 %0, {%1, %2};" : "=l"(d) : "f"(lo), "f"(hi));
    return d;
}
__device__ __forceinline__ void unpack2(u64 v, float& lo, float& hi) {
    asm("mov.b64 {%0, %1}, %2;" : "=f"(lo), "=f"(hi) : "l"(v));
}
__device__ __forceinline__ u64 fma2(u64 a, u64 b, u64 c) {
    u64 d;
    asm("fma.rn.f32x2 %0, %1, %2, %3;" : "=l"(d) : "l"(a), "l"(b), "l"(c));
    return d;
}
__device__ __forceinline__ u64 add2(u64 a, u64 b) {
    u64 d;
    asm("add.rn.f32x2 %0, %1, %2;" : "=l"(d) : "l"(a), "l"(b));
    return d;
}
__device__ __forceinline__ float sqrt_approx(float x) {
    float r;
    asm("sqrt.approx.f32 %0, %1;" : "=f"(r) : "f"(x));
    return r;
}
// min(sqrt(s),10)/10 == sqrt(saturate(s*0.01)):
//  - saturate clamps tiny-negative s (cancellation) to 0 and caps s/100 at 1
//  - the /10 loss-unit cancels exactly -> no FMNMX, no fabs, no final x10
__device__ __forceinline__ float err_term(float s) {
    return sqrt_approx(__saturatef(s * 0.01f));
}

struct __align__(16) F2 { u64 x, y; };   // two packed f32x2 values, LDS.128-able

__global__ void __launch_bounds__(TPB) fape_kernel(
    const float* __restrict__ pred, const float* __restrict__ tru,
    const float* __restrict__ mask, float* __restrict__ out)
{
    // Frame constants for this CTA's 50-frame slice, pre-duplicated for packed math:
    //   sfa[f] = (FxFx, FyFy), sfb[f] = (FzFz, FwFw),  F = (-2*e_f, ||e_f||^2 + eps)
    __shared__ F2 sfa[FPER], sfb[FPER];
    __shared__ float wsum[TPB / 32], wm[TPB / 32];

    const int b     = blockIdx.x >> 3;
    const int chunk = (blockIdx.x >> 1) & 3;
    const int fh    = blockIdx.x & 1;
    const int tid   = threadIdx.x;

    const float* pb = pred + (size_t)b * NPTS * 3;
    const float* tb = tru  + (size_t)b * NPTS * 3;
    const float* mb = mask + (size_t)b * NPTS;

    if (tid < FPER) {
        int f = fh * FPER + tid;
        float ex = pb[3 * f + 0] - tb[3 * f + 0];
        float ey = pb[3 * f + 1] - tb[3 * f + 1];
        float ez = pb[3 * f + 2] - tb[3 * f + 2];
        float nf = fmaf(ex, ex, fmaf(ey, ey, ez * ez)) + 1e-8f;
        float fx = -2.f * ex, fy = -2.f * ey, fz = -2.f * ez;
        F2 a; a.x = pack2(fx, fx); a.y = pack2(fy, fy);
        F2 c; c.x = pack2(fz, fz); c.y = pack2(nf, nf);
        sfa[tid] = a;
        sfb[tid] = c;
    }
    __syncthreads();

    // Four k-points per thread: two packed lanes A=(k0,k1), B=(k2,k3)
    const int kbase = chunk * (TPB * KPT) + tid;
    float ex[KPT], ey[KPT], ez[KPT], nn[KPT];
#pragma unroll
    for (int j = 0; j < KPT; ++j) {
        int k = kbase + j * TPB;
        ex[j] = pb[3 * k + 0] - tb[3 * k + 0];
        ey[j] = pb[3 * k + 1] - tb[3 * k + 1];
        ez[j] = pb[3 * k + 2] - tb[3 * k + 2];
        nn[j] = fmaf(ex[j], ex[j], fmaf(ey[j], ey[j], ez[j] * ez[j]));
    }
    u64 exA = pack2(ex[0], ex[1]), eyA = pack2(ey[0], ey[1]);
    u64 ezA = pack2(ez[0], ez[1]), nA  = pack2(nn[0], nn[1]);
    u64 exB = pack2(ex[2], ex[3]), eyB = pack2(ey[2], ey[3]);
    u64 ezB = pack2(ez[2], ez[3]), nB  = pack2(nn[2], nn[3]);

    float acc0 = 0.f, acc1 = 0.f, acc2 = 0.f, acc3 = 0.f;

#pragma unroll 10
    for (int f = 0; f < FPER; ++f) {
        F2 Fa = sfa[f];   // (FxFx, FyFy)
        F2 Fb = sfb[f];   // (FzFz, FwFw)
        // s = n_k + (n_f + eps) + e_k . (-2 e_f)   (packed, 2 pairs per chain)
        u64 sA = fma2(exA, Fa.x, fma2(eyA, Fa.y, fma2(ezA, Fb.x, add2(nA, Fb.y))));
        u64 sB = fma2(exB, Fa.x, fma2(eyB, Fa.y, fma2(ezB, Fb.x, add2(nB, Fb.y))));
        float s0, s1, s2, s3;
        unpack2(sA, s0, s1);
        unpack2(sB, s2, s3);
        acc0 += err_term(s0);
        acc1 += err_term(s1);
        acc2 += err_term(s2);
        acc3 += err_term(s3);
    }

    float m0 = mb[kbase], m1 = mb[kbase + TPB];
    float m2 = mb[kbase + 2 * TPB], m3 = mb[kbase + 3 * TPB];
    float tsum = fmaf(m0, acc0, fmaf(m1, acc1, fmaf(m2, acc2, m3 * acc3)));
    // mask sum counted once (frame-split duplicates k-coverage): only fh==0 counts
    float msum = (fh == 0) ? ((m0 + m1) + (m2 + m3)) : 0.f;

    // warp reduce
#pragma unroll
    for (int off = 16; off; off >>= 1) {
        tsum += __shfl_down_sync(0xffffffffu, tsum, off);
        msum += __shfl_down_sync(0xffffffffu, msum, off);
    }
    int wid = tid >> 5, lane = tid & 31;
    if (lane == 0) { wsum[wid] = tsum; wm[wid] = msum; }
    __syncthreads();

    if (wid == 0 && lane == 0) {
        float ts = 0.f, ms = 0.f;
#pragma unroll
        for (int w = 0; w < TPB / 32; ++w) { ts += wsum[w]; ms += wm[w]; }
        atomicAdd(&g_sum, (double)ts);
        atomicAdd(&g_msum, (double)ms);
        __threadfence();
        unsigned int done = atomicAdd(&g_count, 1u);
        if (done == GRID - 1) {
            // last CTA: finalize and reset scratch for next graph replay
            // per-pair terms already include the /10 loss unit (saturate form)
            double s = atomicAdd(&g_sum, 0.0);
            double m = atomicAdd(&g_msum, 0.0);
            out[0] = (float)(s / (m + 1e-8));
            g_sum = 0.0;
            g_msum = 0.0;
            g_count = 0u;
        }
    }
}

extern "C" void kernel_launch(void* const* d_in, const int* in_sizes, int n_in,
                              void* d_out, int out_size)
{
    const float* pred = (const float*)d_in[0];
    const float* tru  = (const float*)d_in[1];
    const float* mask = (const float*)d_in[2];
    float* out = (float*)d_out;

    fape_kernel<<<GRID, TPB>>>(pred, tru, mask, out);
}

// round 9
// speedup vs baseline: 1.4125x; 1.4125x over previous
#include <cuda_runtime.h>

#define BATCH   64
#define NPTS    4096
#define CHUNKS  4
#define NFRAMES 100
#define FSPLIT  4
#define FPER    (NFRAMES / FSPLIT)   // 25 frames per CTA
#define TPB     256
#define KPT     4   // NPTS / (CHUNKS*TPB)
#define GRID    (BATCH * CHUNKS * FSPLIT)

__device__ double g_sum;
__device__ double g_msum;
__device__ unsigned int g_count;

typedef unsigned long long u64;

// ---- f32x2 packed helpers (Blackwell sm_100+); packed pair carried as u64 ----
__device__ __forceinline__ u64 pack2(float lo, float hi) {
    u64 d;
    asm("mov.b64 %0, {%1, %2};" : "=l"(d) : "f"(lo), "f"(hi));
    return d;
}
__device__ __forceinline__ void unpack2(u64 v, float& lo, float& hi) {
    asm("mov.b64 {%0, %1}, %2;" : "=f"(lo), "=f"(hi) : "l"(v));
}
__device__ __forceinline__ u64 fma2(u64 a, u64 b, u64 c) {
    u64 d;
    asm("fma.rn.f32x2 %0, %1, %2, %3;" : "=l"(d) : "l"(a), "l"(b), "l"(c));
    return d;
}
__device__ __forceinline__ u64 add2(u64 a, u64 b) {
    u64 d;
    asm("add.rn.f32x2 %0, %1, %2;" : "=l"(d) : "l"(a), "l"(b));
    return d;
}
__device__ __forceinline__ float sqrt_approx(float x) {
    float r;
    asm("sqrt.approx.f32 %0, %1;" : "=f"(r) : "f"(x));
    return r;
}
// min(sqrt(s),10) == sqrt(min(|s|,100)); |s| handles tiny negative s from
// cancellation (|err| ~1e-5) — folds to a single FMNMX with abs modifier.
__device__ __forceinline__ float clamp_s(float s) {
    return fminf(fabsf(s), 100.f);
}

struct F2 { u64 x, y; };   // two packed f32x2 values

__global__ void __launch_bounds__(TPB) fape_kernel(
    const float* __restrict__ pred, const float* __restrict__ tru,
    const float* __restrict__ mask, float* __restrict__ out)
{
    // Frame constants for this CTA's 25-frame slice, pre-duplicated for packed math:
    //   sfa[f] = (FxFx, FyFy), sfb[f] = (FzFz, FwFw),  F = (-2*e_f, ||e_f||^2 + eps)
    __shared__ F2 sfa[FPER], sfb[FPER];
    __shared__ float wsum[TPB / 32], wm[TPB / 32];

    const int b     = blockIdx.x >> 4;
    const int chunk = (blockIdx.x >> 2) & 3;
    const int fh    = blockIdx.x & 3;
    const int tid   = threadIdx.x;

    const float* pb = pred + (size_t)b * NPTS * 3;
    const float* tb = tru  + (size_t)b * NPTS * 3;
    const float* mb = mask + (size_t)b * NPTS;

    if (tid < FPER) {
        int f = fh * FPER + tid;
        float ex = pb[3 * f + 0] - tb[3 * f + 0];
        float ey = pb[3 * f + 1] - tb[3 * f + 1];
        float ez = pb[3 * f + 2] - tb[3 * f + 2];
        float nf = fmaf(ex, ex, fmaf(ey, ey, ez * ez)) + 1e-8f;
        float fx = -2.f * ex, fy = -2.f * ey, fz = -2.f * ez;
        F2 a; a.x = pack2(fx, fx); a.y = pack2(fy, fy);
        F2 c; c.x = pack2(fz, fz); c.y = pack2(nf, nf);
        sfa[tid] = a;
        sfb[tid] = c;
    }
    __syncthreads();

    // Four k-points per thread: two packed lanes A=(k0,k1), B=(k2,k3)
    const int kbase = chunk * (TPB * KPT) + tid;
    float ex[KPT], ey[KPT], ez[KPT], nn[KPT];
#pragma unroll
    for (int j = 0; j < KPT; ++j) {
        int k = kbase + j * TPB;
        ex[j] = pb[3 * k + 0] - tb[3 * k + 0];
        ey[j] = pb[3 * k + 1] - tb[3 * k + 1];
        ez[j] = pb[3 * k + 2] - tb[3 * k + 2];
        nn[j] = fmaf(ex[j], ex[j], fmaf(ey[j], ey[j], ez[j] * ez[j]));
    }
    u64 exA = pack2(ex[0], ex[1]), eyA = pack2(ey[0], ey[1]);
    u64 ezA = pack2(ez[0], ez[1]), nA  = pack2(nn[0], nn[1]);
    u64 exB = pack2(ex[2], ex[3]), eyB = pack2(ey[2], ey[3]);
    u64 ezB = pack2(ez[2], ez[3]), nB  = pack2(nn[2], nn[3]);

    float acc0 = 0.f, acc1 = 0.f, acc2 = 0.f, acc3 = 0.f;

#pragma unroll 5
    for (int f = 0; f < FPER; ++f) {
        F2 Fa = sfa[f];   // (FxFx, FyFy)
        F2 Fb = sfb[f];   // (FzFz, FwFw)
        // s = n_k + (n_f + eps) + e_k . (-2 e_f)   (packed, 2 pairs per chain)
        u64 sA = fma2(exA, Fa.x, fma2(eyA, Fa.y, fma2(ezA, Fb.x, add2(nA, Fb.y))));
        u64 sB = fma2(exB, Fa.x, fma2(eyB, Fa.y, fma2(ezB, Fb.x, add2(nB, Fb.y))));
        float s0, s1, s2, s3;
        unpack2(sA, s0, s1);
        unpack2(sB, s2, s3);
        acc0 += sqrt_approx(clamp_s(s0));
        acc1 += sqrt_approx(clamp_s(s1));
        acc2 += sqrt_approx(clamp_s(s2));
        acc3 += sqrt_approx(clamp_s(s3));
    }

    float m0 = mb[kbase], m1 = mb[kbase + TPB];
    float m2 = mb[kbase + 2 * TPB], m3 = mb[kbase + 3 * TPB];
    float tsum = fmaf(m0, acc0, fmaf(m1, acc1, fmaf(m2, acc2, m3 * acc3)));
    // mask sum counted once (frame-split duplicates k-coverage): only fh==0 counts
    float msum = (fh == 0) ? ((m0 + m1) + (m2 + m3)) : 0.f;

    // warp reduce
#pragma unroll
    for (int off = 16; off; off >>= 1) {
        tsum += __shfl_down_sync(0xffffffffu, tsum, off);
        msum += __shfl_down_sync(0xffffffffu, msum, off);
    }
    int wid = tid >> 5, lane = tid & 31;
    if (lane == 0) { wsum[wid] = tsum; wm[wid] = msum; }
    __syncthreads();

    if (wid == 0 && lane == 0) {
        float ts = 0.f, ms = 0.f;
#pragma unroll
        for (int w = 0; w < TPB / 32; ++w) { ts += wsum[w]; ms += wm[w]; }
        atomicAdd(&g_sum, (double)ts);
        atomicAdd(&g_msum, (double)ms);
        __threadfence();
        unsigned int done = atomicAdd(&g_count, 1u);
        if (done == GRID - 1) {
            // last CTA: finalize and reset scratch for next graph replay
            double s = atomicAdd(&g_sum, 0.0);
            double m = atomicAdd(&g_msum, 0.0);
            out[0] = (float)((s / 10.0) / (m + 1e-8));
            g_sum = 0.0;
            g_msum = 0.0;
            g_count = 0u;
        }
    }
}

extern "C" void kernel_launch(void* const* d_in, const int* in_sizes, int n_in,
                              void* d_out, int out_size)
{
    const float* pred = (const float*)d_in[0];
    const float* tru  = (const float*)d_in[1];
    const float* mask = (const float*)d_in[2];
    float* out = (float*)d_out;

    fape_kernel<<<GRID, TPB>>>(pred, tru, mask, out);
}

// round 10
// speedup vs baseline: 1.5270x; 1.0811x over previous
#include <cuda_runtime.h>

#define BATCH   64
#define NPTS    4096
#define CHUNKS  4
#define NFRAMES 100
#define FSPLIT  4
#define FPER    (NFRAMES / FSPLIT)   // 25 frames per CTA
#define TPB     256
#define KPT     4   // NPTS / (CHUNKS*TPB)
#define GRID    (BATCH * CHUNKS * FSPLIT)

__device__ double g_sum;
__device__ double g_msum;
__device__ unsigned int g_count;

__device__ __forceinline__ float sqrt_approx(float x) {
    float r;
    asm("sqrt.approx.f32 %0, %1;" : "=f"(r) : "f"(x));
    return r;
}
// min(sqrt(s),10) == sqrt(min(|s|,100)); |s| handles tiny negative s from
// cancellation (|err| ~1e-5) — folds to a single FMNMX with abs modifier.
__device__ __forceinline__ float clamp_s(float s) {
    return fminf(fabsf(s), 100.f);
}

__global__ void __launch_bounds__(TPB) fape_kernel(
    const float* __restrict__ pred, const float* __restrict__ tru,
    const float* __restrict__ mask, float* __restrict__ out)
{
    // Frame constants for this CTA's 25-frame slice:
    //   sf[f] = (-2*e_fx, -2*e_fy, -2*e_fz, ||e_f||^2 + eps)
    __shared__ float4 sf[FPER];
    __shared__ float wsum[TPB / 32], wm[TPB / 32];

    const int b     = blockIdx.x >> 4;
    const int chunk = (blockIdx.x >> 2) & 3;
    const int fh    = blockIdx.x & 3;
    const int tid   = threadIdx.x;

    const float* pb = pred + (size_t)b * NPTS * 3;
    const float* tb = tru  + (size_t)b * NPTS * 3;
    const float* mb = mask + (size_t)b * NPTS;

    if (tid < FPER) {
        int f = fh * FPER + tid;
        float ex = pb[3 * f + 0] - tb[3 * f + 0];
        float ey = pb[3 * f + 1] - tb[3 * f + 1];
        float ez = pb[3 * f + 2] - tb[3 * f + 2];
        float nf = fmaf(ex, ex, fmaf(ey, ey, ez * ez)) + 1e-8f;
        sf[tid] = make_float4(-2.f * ex, -2.f * ey, -2.f * ez, nf);
    }
    __syncthreads();

    // Four k-points per thread (independent chains -> ILP for ptxas)
    const int kbase = chunk * (TPB * KPT) + tid;
    float ex[KPT], ey[KPT], ez[KPT], nn[KPT], acc[KPT];
#pragma unroll
    for (int j = 0; j < KPT; ++j) {
        int k = kbase + j * TPB;
        ex[j] = pb[3 * k + 0] - tb[3 * k + 0];
        ey[j] = pb[3 * k + 1] - tb[3 * k + 1];
        ez[j] = pb[3 * k + 2] - tb[3 * k + 2];
        nn[j] = fmaf(ex[j], ex[j], fmaf(ey[j], ey[j], ez[j] * ez[j]));
        acc[j] = 0.f;
    }

#pragma unroll 5
    for (int f = 0; f < FPER; ++f) {
        float4 F = sf[f];
#pragma unroll
        for (int j = 0; j < KPT; ++j) {
            // s = n_k + (n_f + eps) + e_k . (-2 e_f)
            float s = fmaf(ex[j], F.x, fmaf(ey[j], F.y, fmaf(ez[j], F.z, nn[j] + F.w)));
            acc[j] += sqrt_approx(clamp_s(s));
        }
    }

    float m0 = mb[kbase], m1 = mb[kbase + TPB];
    float m2 = mb[kbase + 2 * TPB], m3 = mb[kbase + 3 * TPB];
    float tsum = fmaf(m0, acc[0], fmaf(m1, acc[1], fmaf(m2, acc[2], m3 * acc[3])));
    // mask sum counted once (frame-split duplicates k-coverage): only fh==0 counts
    float msum = (fh == 0) ? ((m0 + m1) + (m2 + m3)) : 0.f;

    // warp reduce
#pragma unroll
    for (int off = 16; off; off >>= 1) {
        tsum += __shfl_down_sync(0xffffffffu, tsum, off);
        msum += __shfl_down_sync(0xffffffffu, msum, off);
    }
    int wid = tid >> 5, lane = tid & 31;
    if (lane == 0) { wsum[wid] = tsum; wm[wid] = msum; }
    __syncthreads();

    if (wid == 0 && lane == 0) {
        float ts = 0.f, ms = 0.f;
#pragma unroll
        for (int w = 0; w < TPB / 32; ++w) { ts += wsum[w]; ms += wm[w]; }
        atomicAdd(&g_sum, (double)ts);
        atomicAdd(&g_msum, (double)ms);
        __threadfence();
        unsigned int done = atomicAdd(&g_count, 1u);
        if (done == GRID - 1) {
            // last CTA: finalize and reset scratch for next graph replay
            double s = atomicAdd(&g_sum, 0.0);
            double m = atomicAdd(&g_msum, 0.0);
            out[0] = (float)((s / 10.0) / (m + 1e-8));
            g_sum = 0.0;
            g_msum = 0.0;
            g_count = 0u;
        }
    }
}

extern "C" void kernel_launch(void* const* d_in, const int* in_sizes, int n_in,
                              void* d_out, int out_size)
{
    const float* pred = (const float*)d_in[0];
    const float* tru  = (const float*)d_in[1];
    const float* mask = (const float*)d_in[2];
    float* out = (float*)d_out;

    fape_kernel<<<GRID, TPB>>>(pred, tru, mask, out);
}